// round 16
// baseline (speedup 1.0000x reference)
#include <cuda_runtime.h>
#include <cuda_bf16.h>

#define NIDS     33                // ids 0..32 (0 = background)
#define NBINS    1089              // 33*33
#define THREADS  512
#define NREP     16                // replicated final histograms
#define MAXCTAS  456               // >= 152 SMs * 3

// Scratch (zero at load; per-CTA hists re-zeroed by owners each call,
// finals + ticket reset by the finalize block).
__device__ int          g_cta[MAXCTAS][NBINS];   // CTA-private L2-resident hists (~2 MB)
__device__ int          g_fin[NREP][NBINS];
__device__ unsigned int g_ticket;

__global__ void __launch_bounds__(THREADS, 3)
fused_iou_kernel(const float4* __restrict__ p4, const float4* __restrict__ t4,
                 int n4,
                 const float* __restrict__ pf, const float* __restrict__ tf,
                 int n, float* __restrict__ out, int nblocks)
{
    __shared__ int   sh[NBINS];
    __shared__ float psum[NIDS], tsum[NIDS], part[NIDS];
    __shared__ int   s_last;

    int  tid  = threadIdx.x;
    int* mine = g_cta[blockIdx.x];

    // zero smem hist + own private global hist (only this CTA touches it)
    for (int b = tid; b < NBINS; b += THREADS) { sh[b] = 0; mine[b] = 0; }
    __threadfence();    // private-hist zeros visible in L2 before any REDG below
    __syncthreads();

    int gid    = blockIdx.x * THREADS + tid;
    int stride = gridDim.x * THREADS;

    // ---- main loop: x,z -> smem ATOMS unit; y,w -> L2 REDG (CTA-private) ----
    int i = gid;
    for (; i + 2 * stride < n4; i += 3 * stride) {
        float4 P0 = p4[i];
        float4 T0 = t4[i];
        float4 P1 = p4[i + stride];
        float4 T1 = t4[i + stride];
        float4 P2 = p4[i + 2 * stride];
        float4 T2 = t4[i + 2 * stride];
        atomicAdd(&sh[(int)fmaf(P0.x, 33.0f, T0.x)], 1);    // bin = 33*p + t (exact fp32)
        atomicAdd(&mine[(int)fmaf(P0.y, 33.0f, T0.y)], 1);  // -> RED.E.ADD, no return
        atomicAdd(&sh[(int)fmaf(P0.z, 33.0f, T0.z)], 1);
        atomicAdd(&mine[(int)fmaf(P0.w, 33.0f, T0.w)], 1);
        atomicAdd(&sh[(int)fmaf(P1.x, 33.0f, T1.x)], 1);
        atomicAdd(&mine[(int)fmaf(P1.y, 33.0f, T1.y)], 1);
        atomicAdd(&sh[(int)fmaf(P1.z, 33.0f, T1.z)], 1);
        atomicAdd(&mine[(int)fmaf(P1.w, 33.0f, T1.w)], 1);
        atomicAdd(&sh[(int)fmaf(P2.x, 33.0f, T2.x)], 1);
        atomicAdd(&mine[(int)fmaf(P2.y, 33.0f, T2.y)], 1);
        atomicAdd(&sh[(int)fmaf(P2.z, 33.0f, T2.z)], 1);
        atomicAdd(&mine[(int)fmaf(P2.w, 33.0f, T2.w)], 1);
    }
    for (; i < n4; i += stride) {
        float4 P = p4[i], T = t4[i];
        atomicAdd(&sh[(int)fmaf(P.x, 33.0f, T.x)], 1);
        atomicAdd(&mine[(int)fmaf(P.y, 33.0f, T.y)], 1);
        atomicAdd(&sh[(int)fmaf(P.z, 33.0f, T.z)], 1);
        atomicAdd(&mine[(int)fmaf(P.w, 33.0f, T.w)], 1);
    }
    __threadfence();    // all this CTA's REDGs ordered before the readback below
    __syncthreads();

    // ---- flush: merge smem hist + own private hist into replicated finals ----
    int rep = blockIdx.x & (NREP - 1);
    for (int b = tid; b < NBINS; b += THREADS) {
        int v = sh[b] + mine[b];    // mine[] written only by this CTA; fenced above
        if (v) atomicAdd(&g_fin[rep][b], v);
    }
    __threadfence();

    // ---- ticket: last block finalizes ----
    if (tid == 0) {
        unsigned int t = atomicAdd(&g_ticket, 1u);
        s_last = (t == (unsigned int)(nblocks - 1));
    }
    __syncthreads();
    if (!s_last) return;

    // reuse sh as the final histogram
    for (int b = tid; b < NBINS; b += THREADS) {
        int s = 0;
        #pragma unroll
        for (int r = 0; r < NREP; r++) { s += g_fin[r][b]; g_fin[r][b] = 0; }
        sh[b] = s;
    }
    __syncthreads();
    if (tid == 0) {
        for (int k = n4 * 4; k < n; k++)               // scalar tail (n % 4)
            sh[(int)fmaf(pf[k], 33.0f, tf[k])]++;
        g_ticket = 0u;
    }
    __syncthreads();

    if (tid < NIDS) {
        int s = 0;
        #pragma unroll
        for (int m = 0; m < NIDS; m++) s += sh[tid * NIDS + m];
        psum[tid] = (float)s;
    } else if (tid >= 64 && tid < 64 + NIDS) {
        int m = tid - 64, s = 0;
        #pragma unroll
        for (int nn = 0; nn < NIDS; nn++) s += sh[nn * NIDS + m];
        tsum[m] = (float)s;
    }
    __syncthreads();

    if (tid >= 1 && tid <= 32) {
        float pn = psum[tid];
        float max_iou = 0.0f;
        #pragma unroll
        for (int m = 1; m < NIDS; m++) {
            float inter = (float)sh[tid * NIDS + m];
            float uni   = pn + tsum[m] - inter;
            float iou   = (uni > 0.0f) ? (inter / uni) : 0.0f;
            max_iou = fmaxf(max_iou, iou);
        }
        part[tid] = 1.0f - max_iou;
    }
    __syncthreads();

    if (tid == 0) {
        float loss = 0.0f;
        for (int nn = 1; nn <= 32; nn++) loss += part[nn];
        double sp = 0.0, st = 0.0;                      // exact dummy term
        for (int id = 1; id < NIDS; id++) {
            sp += (double)id * (double)psum[id];
            st += (double)id * (double)tsum[id];
        }
        loss += (float)((sp + st) * 1e-12);
        out[0] = loss;
    }
}

extern "C" void kernel_launch(void* const* d_in, const int* in_sizes, int n_in,
                              void* d_out, int out_size) {
    const float* pred  = (const float*)d_in[0];
    const float* truem = (const float*)d_in[1];
    float* out = (float*)d_out;
    int n  = in_sizes[0];
    int n4 = n / 4;

    int sm_count = 148;
    cudaDeviceGetAttribute(&sm_count, cudaDevAttrMultiProcessorCount, 0);
    int blocks = sm_count * 3;            // 48 warps/SM (R7 config)
    if (blocks > MAXCTAS) blocks = MAXCTAS;

    fused_iou_kernel<<<blocks, THREADS>>>(
        (const float4*)pred, (const float4*)truem, n4,
        pred, truem, n, out, blocks);
}

// round 17
// speedup vs baseline: 1.7568x; 1.7568x over previous
#include <cuda_runtime.h>
#include <cuda_bf16.h>

#define NIDS    33                 // ids 0..32 (0 = background)
#define NBINS   1089               // 33*33
#define THREADS 512
#define NREP    16                 // replicated global histograms

// Scratch (zero at load; finalize block resets after every call)
__device__ int          g_rep[NREP][NBINS];
__device__ unsigned int g_ticket;

// Address gen for 2 pixels, pure arithmetic (no memory side effects):
// F = P*(132,132) + (T*(4,4) + 2^23)  -> mantissa bits = byte offset 132*p + 4*t
// (132*32 + 4*32 = 4352 < 2^23, all terms exact in fp32)
__device__ __forceinline__ void addr2(unsigned long long Ppair,
                                      unsigned long long Tpair,
                                      unsigned long long C132,
                                      unsigned long long C4,
                                      unsigned long long Cmag,
                                      unsigned& off0, unsigned& off1)
{
    unsigned long long tmp, B;
    asm("fma.rn.f32x2 %0, %1, %2, %3;" : "=l"(tmp) : "l"(Tpair), "l"(C4),   "l"(Cmag));
    asm("fma.rn.f32x2 %0, %1, %2, %3;" : "=l"(B)   : "l"(Ppair), "l"(C132), "l"(tmp));
    off0 = (unsigned)B         & 0x007FFFFFu;
    off1 = (unsigned)(B >> 32) & 0x007FFFFFu;
}

__global__ void __launch_bounds__(THREADS, 3)
fused_iou_kernel(const float4* __restrict__ p4, const float4* __restrict__ t4,
                 int n4,
                 const float* __restrict__ pf, const float* __restrict__ tf,
                 int n, float* __restrict__ out, int nblocks)
{
    __shared__ int   sh[NBINS];
    __shared__ float psum[NIDS], tsum[NIDS], part[NIDS];
    __shared__ int   s_last;

    int tid = threadIdx.x;
    for (int b = tid; b < NBINS; b += THREADS) sh[b] = 0;
    __syncthreads();

    char* shb = (char*)sh;                       // byte-addressed histogram base
    unsigned long long C132, C4, Cmag;
    asm("mov.b64 %0, {%1, %1};" : "=l"(C132) : "f"(132.0f));
    asm("mov.b64 %0, {%1, %1};" : "=l"(C4)   : "f"(4.0f));
    asm("mov.b64 %0, {%1, %1};" : "=l"(Cmag) : "f"(8388608.0f));   // 2^23

    int gid    = blockIdx.x * THREADS + tid;
    int stride = gridDim.x * THREADS;

    // ---- main loop: unroll x3 (6 front-batched LDG.128), FFMA2+LOP3 addresses,
    //      intrinsic atomicAdd (compiler-scheduled ATOMS) ----
    int i = gid;
    for (; i + 2 * stride < n4; i += 3 * stride) {
        float4 P0 = p4[i];
        float4 T0 = t4[i];
        float4 P1 = p4[i + stride];
        float4 T1 = t4[i + stride];
        float4 P2 = p4[i + 2 * stride];
        float4 T2 = t4[i + 2 * stride];
        const unsigned long long* Pw0 = (const unsigned long long*)&P0;
        const unsigned long long* Tw0 = (const unsigned long long*)&T0;
        const unsigned long long* Pw1 = (const unsigned long long*)&P1;
        const unsigned long long* Tw1 = (const unsigned long long*)&T1;
        const unsigned long long* Pw2 = (const unsigned long long*)&P2;
        const unsigned long long* Tw2 = (const unsigned long long*)&T2;

        unsigned a0, a1, a2, a3, a4, a5, a6, a7, a8, a9, aA, aB;
        addr2(Pw0[0], Tw0[0], C132, C4, Cmag, a0, a1);
        addr2(Pw0[1], Tw0[1], C132, C4, Cmag, a2, a3);
        addr2(Pw1[0], Tw1[0], C132, C4, Cmag, a4, a5);
        addr2(Pw1[1], Tw1[1], C132, C4, Cmag, a6, a7);
        addr2(Pw2[0], Tw2[0], C132, C4, Cmag, a8, a9);
        addr2(Pw2[1], Tw2[1], C132, C4, Cmag, aA, aB);

        atomicAdd((int*)(shb + a0), 1);
        atomicAdd((int*)(shb + a1), 1);
        atomicAdd((int*)(shb + a2), 1);
        atomicAdd((int*)(shb + a3), 1);
        atomicAdd((int*)(shb + a4), 1);
        atomicAdd((int*)(shb + a5), 1);
        atomicAdd((int*)(shb + a6), 1);
        atomicAdd((int*)(shb + a7), 1);
        atomicAdd((int*)(shb + a8), 1);
        atomicAdd((int*)(shb + a9), 1);
        atomicAdd((int*)(shb + aA), 1);
        atomicAdd((int*)(shb + aB), 1);
    }
    for (; i < n4; i += stride) {
        float4 P = p4[i], T = t4[i];
        const unsigned long long* Pw = (const unsigned long long*)&P;
        const unsigned long long* Tw = (const unsigned long long*)&T;
        unsigned a0, a1, a2, a3;
        addr2(Pw[0], Tw[0], C132, C4, Cmag, a0, a1);
        addr2(Pw[1], Tw[1], C132, C4, Cmag, a2, a3);
        atomicAdd((int*)(shb + a0), 1);
        atomicAdd((int*)(shb + a1), 1);
        atomicAdd((int*)(shb + a2), 1);
        atomicAdd((int*)(shb + a3), 1);
    }
    __syncthreads();

    // ---- flush block hist into replicated global hists ----
    int rep = blockIdx.x & (NREP - 1);
    for (int b = tid; b < NBINS; b += THREADS) {
        int v = sh[b];
        if (v) atomicAdd(&g_rep[rep][b], v);
    }
    __threadfence();

    // ---- ticket: last block finalizes ----
    if (tid == 0) {
        unsigned int t = atomicAdd(&g_ticket, 1u);
        s_last = (t == (unsigned int)(nblocks - 1));
    }
    __syncthreads();
    if (!s_last) return;

    // reuse sh as the final histogram
    for (int b = tid; b < NBINS; b += THREADS) {
        int s = 0;
        #pragma unroll
        for (int r = 0; r < NREP; r++) { s += g_rep[r][b]; g_rep[r][b] = 0; }
        sh[b] = s;
    }
    __syncthreads();
    if (tid == 0) {
        for (int k = n4 * 4; k < n; k++)               // scalar tail (n % 4)
            sh[(int)fmaf(pf[k], 33.0f, tf[k])]++;
        g_ticket = 0u;
    }
    __syncthreads();

    if (tid < NIDS) {
        int s = 0;
        #pragma unroll
        for (int m = 0; m < NIDS; m++) s += sh[tid * NIDS + m];
        psum[tid] = (float)s;
    } else if (tid >= 64 && tid < 64 + NIDS) {
        int m = tid - 64, s = 0;
        #pragma unroll
        for (int nn = 0; nn < NIDS; nn++) s += sh[nn * NIDS + m];
        tsum[m] = (float)s;
    }
    __syncthreads();

    if (tid >= 1 && tid <= 32) {
        float pn = psum[tid];
        float max_iou = 0.0f;
        #pragma unroll
        for (int m = 1; m < NIDS; m++) {
            float inter = (float)sh[tid * NIDS + m];
            float uni   = pn + tsum[m] - inter;
            float iou   = (uni > 0.0f) ? (inter / uni) : 0.0f;
            max_iou = fmaxf(max_iou, iou);
        }
        part[tid] = 1.0f - max_iou;
    }
    __syncthreads();

    if (tid == 0) {
        float loss = 0.0f;
        for (int nn = 1; nn <= 32; nn++) loss += part[nn];
        double sp = 0.0, st = 0.0;                      // exact dummy term
        for (int id = 1; id < NIDS; id++) {
            sp += (double)id * (double)psum[id];
            st += (double)id * (double)tsum[id];
        }
        loss += (float)((sp + st) * 1e-12);
        out[0] = loss;
    }
}

extern "C" void kernel_launch(void* const* d_in, const int* in_sizes, int n_in,
                              void* d_out, int out_size) {
    const float* pred  = (const float*)d_in[0];
    const float* truem = (const float*)d_in[1];
    float* out = (float*)d_out;
    int n  = in_sizes[0];
    int n4 = n / 4;

    int sm_count = 148;
    cudaDeviceGetAttribute(&sm_count, cudaDevAttrMultiProcessorCount, 0);
    int blocks = sm_count * 3;   // 3 CTAs/SM x 512 thr = 48 warps/SM (R7 config)

    fused_iou_kernel<<<blocks, THREADS>>>(
        (const float4*)pred, (const float4*)truem, n4,
        pred, truem, n, out, blocks);
}